// round 6
// baseline (speedup 1.0000x reference)
#include <cuda_runtime.h>
#include <cstdint>

#define MDIM 8192
#define KDIM 8192
#define NDIM 8192

#define ROW_TILES 148   // one row-tile per SM-resident block slot
#define COL_TILES 8     // 8 * 256 threads * float4 = 8192 columns

// ---- scratch (device globals; no allocation allowed) ----
__device__ float g_partial[ROW_TILES * KDIM]; // 4.6 MiB, overwritten each launch
__device__ float g_wcs[KDIM];                 // 32 KiB column-sum of W

// ============================================================
// Kernel 1: partial column sums of W. (stable: ~41.5us, 6.5+ TB/s)
// Grid: exactly COL_TILES * ROW_TILES = 1184 blocks = 8 per SM.
// ============================================================
__global__ __launch_bounds__(256, 8) void colsum_partial(const float* __restrict__ w) {
    const int bid  = blockIdx.x;
    const int col4 = (bid & (COL_TILES - 1)) * 256 + threadIdx.x;
    const int rt   = bid >> 3;

    const float4* wp = reinterpret_cast<const float4*>(w) + col4;

    float4 acc = make_float4(0.f, 0.f, 0.f, 0.f);
    #pragma unroll 4
    for (int r = rt; r < NDIM; r += ROW_TILES) {
        float4 v = __ldcs(wp + (size_t)r * (KDIM / 4));
        acc.x += v.x; acc.y += v.y; acc.z += v.z; acc.w += v.w;
    }
    reinterpret_cast<float4*>(g_partial)[(size_t)rt * (KDIM / 4) + col4] = acc;
}

// ============================================================
// Kernel 2: fold the 148 partials -> g_wcs (4.6 MiB read).
// ============================================================
__global__ __launch_bounds__(256) void colsum_reduce() {
    const int k = blockIdx.x * 256 + threadIdx.x;
    float s = 0.f;
    #pragma unroll 4
    for (int rt = 0; rt < ROW_TILES; ++rt)
        s += g_partial[(size_t)rt * KDIM + k];
    g_wcs[k] = s;
}

// ============================================================
// Kernel 3: y[m] = 0.75 * dot(x[m,:], wcs).
// 2 rows per block, INTERLEAVED in one loop: per iteration
// 3 independent LDG.128 (x-row0, x-row1, shared wcs) -> 24
// outstanding loads/thread at unroll 8, two independent FFMA
// accumulators, wcs L2 traffic halved. 4096 blocks.
// ============================================================
__global__ __launch_bounds__(256) void rowdot(const float* __restrict__ x,
                                              float* __restrict__ y) {
    const int tid  = threadIdx.x;
    const int row0 = blockIdx.x * 2;
    const float4* xp0 = reinterpret_cast<const float4*>(x) + (size_t)row0 * (KDIM / 4);
    const float4* xp1 = xp0 + (KDIM / 4);
    const float4* wp  = reinterpret_cast<const float4*>(g_wcs);

    float4 acc0 = make_float4(0.f, 0.f, 0.f, 0.f);
    float4 acc1 = make_float4(0.f, 0.f, 0.f, 0.f);
    #pragma unroll 8
    for (int i = tid; i < KDIM / 4; i += 256) {
        float4 b  = wp[i];            // hot: L1/L2-resident
        float4 a0 = __ldcs(xp0 + i);  // one-touch streaming
        float4 a1 = __ldcs(xp1 + i);  // one-touch streaming
        acc0.x += a0.x * b.x; acc0.y += a0.y * b.y;
        acc0.z += a0.z * b.z; acc0.w += a0.w * b.w;
        acc1.x += a1.x * b.x; acc1.y += a1.y * b.y;
        acc1.z += a1.z * b.z; acc1.w += a1.w * b.w;
    }
    float s0 = (acc0.x + acc0.y) + (acc0.z + acc0.w);
    float s1 = (acc1.x + acc1.y) + (acc1.z + acc1.w);

    #pragma unroll
    for (int off = 16; off > 0; off >>= 1) {
        s0 += __shfl_xor_sync(0xFFFFFFFFu, s0, off);
        s1 += __shfl_xor_sync(0xFFFFFFFFu, s1, off);
    }

    __shared__ float red[8][2];
    const int warp = tid >> 5;
    const int lane = tid & 31;
    if (lane == 0) { red[warp][0] = s0; red[warp][1] = s1; }
    __syncthreads();
    if (warp == 0 && lane < 8) {
        float t0 = red[lane][0];
        float t1 = red[lane][1];
        #pragma unroll
        for (int off = 4; off > 0; off >>= 1) {
            t0 += __shfl_xor_sync(0xFFu, t0, off);
            t1 += __shfl_xor_sync(0xFFu, t1, off);
        }
        if (lane == 0) {
            y[row0]     = 0.75f * t0;
            y[row0 + 1] = 0.75f * t1;
        }
    }
}

extern "C" void kernel_launch(void* const* d_in, const int* in_sizes, int n_in,
                              void* d_out, int out_size) {
    const float* x = (const float*)d_in[0];  // [M, K]
    const float* w = (const float*)d_in[1];  // [N, K]
    float* y = (float*)d_out;                // [M, 1]

    colsum_partial<<<COL_TILES * ROW_TILES, 256>>>(w);
    colsum_reduce<<<KDIM / 256, 256>>>();
    rowdot<<<MDIM / 2, 256>>>(x, y);
}